// round 17
// baseline (speedup 1.0000x reference)
#include <cuda_runtime.h>
#include <cstdint>

// Trilinear resize [4,128,128,128,2] f32 -> [4,192,192,192,2] f32, zoom=1.5.
// Experiment: TMA bulk stores (cp.async.bulk shared->global) to take the
// output write stream OFF the per-thread L1/LSU STG path.
// Compute identical to the committed kernel (R13); results staged in a smem
// output tile, then 9 x 1536B contiguous rows DMA'd to gmem by one thread.

#define IN_D  128
#define OUT_D 192

__device__ __forceinline__ float2 lerp2(float2 a, float2 b, float wa, float wb) {
    return make_float2(fmaf(a.x, wa, b.x * wb), fmaf(a.y, wa, b.y * wb));
}

__global__ __launch_bounds__(192) void resize_tma_store_kernel(
    const float2* __restrict__ in,   // [4,128,128,128] voxels (C=2 packed)
    float2* __restrict__ out)        // [4,192,192,192] voxels
{
    __shared__ float2 tile[9][IN_D];     // input stage, 9216 B
    __shared__ __align__(16) float2 otile[9][OUT_D];  // output stage, 13824 B
    float4* tile4 = (float4*)tile;

    const int blk = blockIdx.x;
    const int yk = blk & 63;
    const int zk = (blk >> 6) & 63;
    const int b  = blk >> 12;

    const int tid = threadIdx.x;         // 0..191

    // ---- Phase 1: cooperative float4 load of 9 input rows ----
    {
        const float4* in4 =
            (const float4*)(in + (size_t)b * (IN_D * IN_D * IN_D));
        const int lf4 = tid & 63;
        const int yi  = tid >> 6;        // 0..2
        const int y   = min(2 * yk + yi, IN_D - 1);
        #pragma unroll
        for (int zi = 0; zi < 3; zi++) {
            int z = min(2 * zk + zi, IN_D - 1);
            tile4[(zi * 3 + yi) * 64 + lf4] =
                __ldg(in4 + ((size_t)z * IN_D + y) * 64 + lf4);
        }
    }
    __syncthreads();

    // ---- Phase 2: x-lerp from smem, y/z lerp in registers ----
    const float c13 = 1.0f / 3.0f;
    const float c23 = 2.0f / 3.0f;

    const int k  = tid / 3;
    const int xo = tid - 3 * k;

    int xA, xB;
    float wA;
    if (xo == 0)      { xA = 2 * k;     xB = xA;                     wA = 1.0f; }
    else if (xo == 1) { xA = 2 * k;     xB = 2 * k + 1;              wA = c13;  }
    else              { xA = 2 * k + 1; xB = min(2 * k + 2, IN_D-1); wA = c23;  }
    const float wB = 1.0f - wA;

    float2 xl[9];
    #pragma unroll
    for (int r = 0; r < 9; r++) {
        float2 a = tile[r][xA];
        float2 c = tile[r][xB];
        xl[r] = lerp2(a, c, wA, wB);
    }

    float2 yl[3][3];
    #pragma unroll
    for (int zi = 0; zi < 3; zi++) {
        float2 v0 = xl[3 * zi + 0];
        float2 v1 = xl[3 * zi + 1];
        float2 v2 = xl[3 * zi + 2];
        yl[zi][0] = v0;
        yl[zi][1] = lerp2(v0, v1, c13, c23);
        yl[zi][2] = lerp2(v1, v2, c23, c13);
    }

    // ---- z-lerp into the smem output tile (conflict-free STS.64) ----
    #pragma unroll
    for (int yo = 0; yo < 3; yo++) {
        float2 v0 = yl[0][yo];
        float2 v1 = yl[1][yo];
        float2 v2 = yl[2][yo];
        otile[0 * 3 + yo][tid] = v0;
        otile[1 * 3 + yo][tid] = lerp2(v0, v1, c13, c23);
        otile[2 * 3 + yo][tid] = lerp2(v1, v2, c23, c13);
    }
    __syncthreads();

    // ---- TMA bulk stores: 9 contiguous 1536B rows, issued by one thread ----
    if (tid == 0) {
        asm volatile("fence.proxy.async.shared::cta;" ::: "memory");
        float2* obase = out +
            ((((size_t)b * OUT_D + 3 * zk) * OUT_D + 3 * yk) * OUT_D);
        #pragma unroll
        for (int r = 0; r < 9; r++) {
            int zo = r / 3;
            int yo = r - 3 * zo;
            float2* g = obase + ((size_t)zo * OUT_D + yo) * OUT_D;
            uint32_t s;
            asm("{ .reg .u64 a; cvta.to.shared.u64 a, %1; cvt.u32.u64 %0, a; }"
                : "=r"(s) : "l"(&otile[r][0]));
            asm volatile(
                "cp.async.bulk.global.shared::cta.bulk_group [%0], [%1], %2;"
                :: "l"(g), "r"(s), "r"(OUT_D * 8) : "memory");
        }
        asm volatile("cp.async.bulk.commit_group;" ::: "memory");
        asm volatile("cp.async.bulk.wait_group 0;" ::: "memory");
    }
}

extern "C" void kernel_launch(void* const* d_in, const int* in_sizes, int n_in,
                              void* d_out, int out_size) {
    const float2* in = (const float2*)d_in[0];
    float2* out = (float2*)d_out;

    int blocks = 4 * 64 * 64;   // (b, zk, yk) = 16384
    resize_tma_store_kernel<<<blocks, 192>>>(in, out);
}